// round 8
// baseline (speedup 1.0000x reference)
#include <cuda_runtime.h>
#include <cstdint>

#define D_DIM  448
#define MTOT   32768
#define BM     64
#define BN     112
#define BK     32
#define NSTG   3
#define A_STRIDE 36                        // conflict-free scalar frag LDS
#define B_STRIDE 40                        // conflict-free v2 frag LDS
#define AS_F   (BM * A_STRIDE)             // 2304
#define BS_F   (BN * B_STRIDE)             // 4480
#define STG_F  (AS_F + BS_F)               // 6784
#define SMEM_BYTES (NSTG * STG_F * 4)      // 81408 -> 2 CTAs/SM

// W_eff transposed [n][k_perm], tf32-rounded. perm in 8-block: j<4 ? 2j : 2(j-4)+1
__device__ __align__(16) float g_W[D_DIM * D_DIM];

// ---- helpers ----------------------------------------------------------------
__device__ __forceinline__ uint32_t smem_u32(const void* p) {
    uint32_t a;
    asm("{ .reg .u64 t; cvta.to.shared.u64 t, %1; cvt.u32.u64 %0, t; }" : "=r"(a) : "l"(p));
    return a;
}
__device__ __forceinline__ uint32_t f2tf32(float f) {
    uint32_t r;
    asm("cvt.rna.tf32.f32 %0, %1;" : "=r"(r) : "f"(f));
    return r;
}
__device__ __forceinline__ void mma_tf32(float* c, const uint32_t* a, uint32_t b0, uint32_t b1) {
    asm volatile(
        "mma.sync.aligned.m16n8k8.row.col.f32.tf32.tf32.f32 "
        "{%0,%1,%2,%3}, {%4,%5,%6,%7}, {%8,%9}, {%0,%1,%2,%3};"
        : "+f"(c[0]), "+f"(c[1]), "+f"(c[2]), "+f"(c[3])
        : "r"(a[0]), "r"(a[1]), "r"(a[2]), "r"(a[3]), "r"(b0), "r"(b1));
}
#define CP16(dst, src) \
    asm volatile("cp.async.cg.shared.global [%0], [%1], 16;" :: "r"(dst), "l"(src) : "memory")
#define CP_COMMIT() asm volatile("cp.async.commit_group;" ::: "memory")
#define CP_WAIT1()  asm volatile("cp.async.wait_group 1;" ::: "memory")

// ---------------------------------------------------------------------------
// Prep: W_eff = (Wq*diagA + Wk*diagB + Wv*diagC) @ Wo, transposed + k-permuted
// + tf32 into g_W.  32x32 tiles, grid (14,14), 256 threads, 2x2 per thread.
// Global loads REGISTER-PREFETCHED one iteration ahead (hides L2/DRAM latency
// under the 32-step FMA phase).
// ---------------------------------------------------------------------------
__global__ void __launch_bounds__(256) weff_kernel(const float* __restrict__ Wq,
                                                   const float* __restrict__ Wk,
                                                   const float* __restrict__ Wv,
                                                   const float* __restrict__ Wo,
                                                   const float* __restrict__ A,
                                                   const float* __restrict__ Bm,
                                                   const float* __restrict__ C) {
    __shared__ float dg[3][D_DIM];
    __shared__ float Ms[32][33];   // [k-row][d]
    __shared__ float Ws[32][33];   // [d][n]
    const int tid = threadIdx.x;
    for (int i = tid; i < D_DIM; i += 256) {
        dg[0][i] = A[(size_t)i * D_DIM + i];
        dg[1][i] = Bm[(size_t)i * D_DIM + i];
        dg[2][i] = C[(size_t)i * D_DIM + i];
    }

    const int ty = tid >> 4, tx = tid & 15;
    const int k0 = blockIdx.y * 32;
    const int n0 = blockIdx.x * 32;
    const int lrow = tid >> 3;          // 0..31
    const int lc4  = (tid & 7) * 4;     // 0,4,..28

    const size_t qoff = (size_t)(k0 + lrow) * D_DIM + lc4;
    const size_t ooff = (size_t)lrow * D_DIM + n0 + lc4;

    // prefetch iter 0
    float4 pq = *reinterpret_cast<const float4*>(Wq + qoff);
    float4 pk = *reinterpret_cast<const float4*>(Wk + qoff);
    float4 pv = *reinterpret_cast<const float4*>(Wv + qoff);
    float4 po = *reinterpret_cast<const float4*>(Wo + ooff);
    __syncthreads();   // also covers dg[] stores

    float acc[2][2] = {};
    for (int kt = 0; kt < D_DIM; kt += 32) {
        {
            const float4 da = *reinterpret_cast<const float4*>(&dg[0][kt + lc4]);
            const float4 db = *reinterpret_cast<const float4*>(&dg[1][kt + lc4]);
            const float4 dc = *reinterpret_cast<const float4*>(&dg[2][kt + lc4]);
            Ms[lrow][lc4 + 0] = pq.x * da.x + pk.x * db.x + pv.x * dc.x;
            Ms[lrow][lc4 + 1] = pq.y * da.y + pk.y * db.y + pv.y * dc.y;
            Ms[lrow][lc4 + 2] = pq.z * da.z + pk.z * db.z + pv.z * dc.z;
            Ms[lrow][lc4 + 3] = pq.w * da.w + pk.w * db.w + pv.w * dc.w;
            Ws[lrow][lc4 + 0] = po.x; Ws[lrow][lc4 + 1] = po.y;
            Ws[lrow][lc4 + 2] = po.z; Ws[lrow][lc4 + 3] = po.w;
        }
        __syncthreads();

        // prefetch next iteration (overlaps the FMA phase below)
        if (kt + 32 < D_DIM) {
            pq = *reinterpret_cast<const float4*>(Wq + qoff + kt + 32);
            pk = *reinterpret_cast<const float4*>(Wk + qoff + kt + 32);
            pv = *reinterpret_cast<const float4*>(Wv + qoff + kt + 32);
            po = *reinterpret_cast<const float4*>(Wo + ooff + (size_t)(kt + 32) * D_DIM);
        }

#pragma unroll
        for (int kk = 0; kk < 32; kk++) {
            const float a0 = Ms[ty][kk],      a1 = Ms[ty + 16][kk];
            const float b0 = Ws[kk][tx],      b1 = Ws[kk][tx + 16];
            acc[0][0] += a0 * b0; acc[0][1] += a0 * b1;
            acc[1][0] += a1 * b0; acc[1][1] += a1 * b1;
        }
        __syncthreads();
    }
#pragma unroll
    for (int i = 0; i < 2; i++) {
        const int k = k0 + ty + i * 16;
        const int j = k & 7;
        const int kp = (k & ~7) | (j < 4 ? 2 * j : 2 * (j - 4) + 1);
#pragma unroll
        for (int jj = 0; jj < 2; jj++) {
            const int n = n0 + tx + jj * 16;
            g_W[(size_t)n * D_DIM + kp] = __uint_as_float(f2tf32(acc[i][jj]));
        }
    }
}

// ---------------------------------------------------------------------------
// Main GEMM: out = x @ W_eff, tf32 mma.sync.
// BM=64, BN=112, BK=32 -> grid 2048 (6.92 waves at 2 CTAs/SM, ~1% tail).
// 3-stage cp.async, 256 threads (4m x 2n warps), warp tile 16x56,
// single sync per mainloop iteration.
// ---------------------------------------------------------------------------
__global__ void __launch_bounds__(256, 2) gemm_tf32_kernel(const float* __restrict__ x,
                                                           float* __restrict__ out) {
    extern __shared__ __align__(16) float smem[];

    const int tid   = threadIdx.x;
    const int wid   = tid >> 5;
    const int lane  = tid & 31;
    const int g     = lane >> 2;
    const int t     = lane & 3;
    const int warpM = wid & 3;     // 16 rows each
    const int warpN = wid >> 2;    // 56 cols each

    const int m0 = blockIdx.y * BM;
    const int n0 = blockIdx.x * BN;

    const uint32_t smem_base = smem_u32(smem);

    float acc[7][4];
#pragma unroll
    for (int j = 0; j < 7; j++)
#pragma unroll
        for (int q = 0; q < 4; q++) acc[j][q] = 0.f;

    auto load_stage = [&](int s, int kt) {
        const uint32_t aBase = smem_base + (uint32_t)(s * STG_F) * 4u;
        const uint32_t bBase = aBase + (uint32_t)AS_F * 4u;
        // A: 64x32 = 512 chunks, 2 per thread
#pragma unroll
        for (int j = 0; j < 2; j++) {
            const int id  = tid + j * 256;
            const int row = id >> 3;
            const int c   = id & 7;
            CP16(aBase + (uint32_t)(row * A_STRIDE + c * 4) * 4u,
                 x + (size_t)(m0 + row) * D_DIM + kt + c * 4);
        }
        // B: 112x32 = 896 chunks, 3 per thread + 128 extra
#pragma unroll
        for (int j = 0; j < 3; j++) {
            const int id  = tid + j * 256;
            const int row = id >> 3;
            const int c   = id & 7;
            CP16(bBase + (uint32_t)(row * B_STRIDE + c * 4) * 4u,
                 g_W + (size_t)(n0 + row) * D_DIM + kt + c * 4);
        }
        if (tid < 128) {
            const int id  = tid + 768;
            const int row = id >> 3;
            const int c   = id & 7;
            CP16(bBase + (uint32_t)(row * B_STRIDE + c * 4) * 4u,
                 g_W + (size_t)(n0 + row) * D_DIM + kt + c * 4);
        }
    };

    load_stage(0, 0);
    CP_COMMIT();
    load_stage(1, BK);
    CP_COMMIT();

    const int NIT = D_DIM / BK;   // 14
#pragma unroll 1
    for (int it = 0; it < NIT; it++) {
        CP_WAIT1();
        __syncthreads();

        if (it + 2 < NIT) load_stage((it + 2) % NSTG, (it + 2) * BK);
        CP_COMMIT();

        const float* As = smem + (it % NSTG) * STG_F;
        const float* Bs = As + AS_F;
        const float* Arow = As + (warpM * 16 + g) * A_STRIDE;
        const float* Brow = Bs + (warpN * 56 + g) * B_STRIDE;

#pragma unroll
        for (int kk = 0; kk < 4; kk++) {
            const int k0 = kk * 8;
            uint32_t af[4];
            af[0] = f2tf32(Arow[k0 + t]);
            af[1] = f2tf32(Arow[8 * A_STRIDE + k0 + t]);
            af[2] = f2tf32(Arow[k0 + t + 4]);
            af[3] = f2tf32(Arow[8 * A_STRIDE + k0 + t + 4]);
#pragma unroll
            for (int ni = 0; ni < 7; ni++) {
                // permuted layout: logical (k0+t, k0+t+4) at floats (k0+2t, k0+2t+1)
                const float2 bv = *reinterpret_cast<const float2*>(
                    Brow + ni * 8 * B_STRIDE + k0 + 2 * t);
                mma_tf32(acc[ni], af, __float_as_uint(bv.x), __float_as_uint(bv.y));
            }
        }
        // no trailing sync: next iteration's top sync provides the ordering
    }

    // ---- epilogue: rows (g, g+8), cols (2t, 2t+1) per ni
    const int r0 = m0 + warpM * 16 + g;
#pragma unroll
    for (int ni = 0; ni < 7; ni++) {
        const int c0 = n0 + warpN * 56 + ni * 8 + 2 * t;
        float2 v0, v1;
        v0.x = acc[ni][0]; v0.y = acc[ni][1];
        v1.x = acc[ni][2]; v1.y = acc[ni][3];
        *reinterpret_cast<float2*>(out + (size_t)r0 * D_DIM + c0)       = v0;
        *reinterpret_cast<float2*>(out + (size_t)(r0 + 8) * D_DIM + c0) = v1;
    }
}

// ---------------------------------------------------------------------------
extern "C" void kernel_launch(void* const* d_in, const int* in_sizes, int n_in,
                              void* d_out, int out_size) {
    const float* x  = (const float*)d_in[0];
    const float* Wq = (const float*)d_in[1];
    const float* Wk = (const float*)d_in[2];
    const float* Wv = (const float*)d_in[3];
    const float* Wo = (const float*)d_in[4];
    const float* A  = (const float*)d_in[5];
    const float* B  = (const float*)d_in[6];
    const float* C  = (const float*)d_in[7];

    cudaFuncSetAttribute(gemm_tf32_kernel, cudaFuncAttributeMaxDynamicSharedMemorySize,
                         SMEM_BYTES);

    weff_kernel<<<dim3(D_DIM / 32, D_DIM / 32), 256>>>(Wq, Wk, Wv, Wo, A, B, C);
    gemm_tf32_kernel<<<dim3(D_DIM / BN, MTOT / BM), 256, SMEM_BYTES>>>(x, (float*)d_out);
}

// round 9
// speedup vs baseline: 1.0573x; 1.0573x over previous
#include <cuda_runtime.h>
#include <cstdint>

#define D_DIM  448
#define MTOT   32768
#define BM     128
#define BN     112
#define BK     32
#define NSTG   3
#define NTHR   512
#define A_STRIDE 36                        // conflict-free scalar frag LDS
#define B_STRIDE 40                        // conflict-free v2 frag LDS
#define AS_F   (BM * A_STRIDE)             // 4608
#define BS_F   (BN * B_STRIDE)             // 4480
#define STG_F  (AS_F + BS_F)               // 9088
#define SMEM_BYTES (NSTG * STG_F * 4)      // 109056 -> 2 CTAs/SM

// W_eff transposed [n][k_perm], tf32-rounded. perm in 8-block: j<4 ? 2j : 2(j-4)+1
__device__ __align__(16) float g_W[D_DIM * D_DIM];

// ---- helpers ----------------------------------------------------------------
__device__ __forceinline__ uint32_t smem_u32(const void* p) {
    uint32_t a;
    asm("{ .reg .u64 t; cvta.to.shared.u64 t, %1; cvt.u32.u64 %0, t; }" : "=r"(a) : "l"(p));
    return a;
}
__device__ __forceinline__ uint32_t f2tf32(float f) {
    uint32_t r;
    asm("cvt.rna.tf32.f32 %0, %1;" : "=r"(r) : "f"(f));
    return r;
}
__device__ __forceinline__ void mma_tf32(float* c, const uint32_t* a, uint32_t b0, uint32_t b1) {
    asm volatile(
        "mma.sync.aligned.m16n8k8.row.col.f32.tf32.tf32.f32 "
        "{%0,%1,%2,%3}, {%4,%5,%6,%7}, {%8,%9}, {%0,%1,%2,%3};"
        : "+f"(c[0]), "+f"(c[1]), "+f"(c[2]), "+f"(c[3])
        : "r"(a[0]), "r"(a[1]), "r"(a[2]), "r"(a[3]), "r"(b0), "r"(b1));
}
#define CP16(dst, src) \
    asm volatile("cp.async.cg.shared.global [%0], [%1], 16;" :: "r"(dst), "l"(src) : "memory")
#define CP_COMMIT() asm volatile("cp.async.commit_group;" ::: "memory")
#define CP_WAIT1()  asm volatile("cp.async.wait_group 1;" ::: "memory")

// ---------------------------------------------------------------------------
// Prep: W_eff = (Wq*diagA + Wk*diagB + Wv*diagC) @ Wo, transposed + k-permuted
// + tf32 into g_W.  32x32 tiles, grid (14,14), 256 threads, 2x2 per thread,
// register-prefetched global loads. (Unchanged from round 8 — measured good.)
// ---------------------------------------------------------------------------
__global__ void __launch_bounds__(256) weff_kernel(const float* __restrict__ Wq,
                                                   const float* __restrict__ Wk,
                                                   const float* __restrict__ Wv,
                                                   const float* __restrict__ Wo,
                                                   const float* __restrict__ A,
                                                   const float* __restrict__ Bm,
                                                   const float* __restrict__ C) {
    __shared__ float dg[3][D_DIM];
    __shared__ float Ms[32][33];
    __shared__ float Ws[32][33];
    const int tid = threadIdx.x;
    for (int i = tid; i < D_DIM; i += 256) {
        dg[0][i] = A[(size_t)i * D_DIM + i];
        dg[1][i] = Bm[(size_t)i * D_DIM + i];
        dg[2][i] = C[(size_t)i * D_DIM + i];
    }

    const int ty = tid >> 4, tx = tid & 15;
    const int k0 = blockIdx.y * 32;
    const int n0 = blockIdx.x * 32;
    const int lrow = tid >> 3;
    const int lc4  = (tid & 7) * 4;

    const size_t qoff = (size_t)(k0 + lrow) * D_DIM + lc4;
    const size_t ooff = (size_t)lrow * D_DIM + n0 + lc4;

    float4 pq = *reinterpret_cast<const float4*>(Wq + qoff);
    float4 pk = *reinterpret_cast<const float4*>(Wk + qoff);
    float4 pv = *reinterpret_cast<const float4*>(Wv + qoff);
    float4 po = *reinterpret_cast<const float4*>(Wo + ooff);
    __syncthreads();

    float acc[2][2] = {};
    for (int kt = 0; kt < D_DIM; kt += 32) {
        {
            const float4 da = *reinterpret_cast<const float4*>(&dg[0][kt + lc4]);
            const float4 db = *reinterpret_cast<const float4*>(&dg[1][kt + lc4]);
            const float4 dc = *reinterpret_cast<const float4*>(&dg[2][kt + lc4]);
            Ms[lrow][lc4 + 0] = pq.x * da.x + pk.x * db.x + pv.x * dc.x;
            Ms[lrow][lc4 + 1] = pq.y * da.y + pk.y * db.y + pv.y * dc.y;
            Ms[lrow][lc4 + 2] = pq.z * da.z + pk.z * db.z + pv.z * dc.z;
            Ms[lrow][lc4 + 3] = pq.w * da.w + pk.w * db.w + pv.w * dc.w;
            Ws[lrow][lc4 + 0] = po.x; Ws[lrow][lc4 + 1] = po.y;
            Ws[lrow][lc4 + 2] = po.z; Ws[lrow][lc4 + 3] = po.w;
        }
        __syncthreads();

        if (kt + 32 < D_DIM) {
            pq = *reinterpret_cast<const float4*>(Wq + qoff + kt + 32);
            pk = *reinterpret_cast<const float4*>(Wk + qoff + kt + 32);
            pv = *reinterpret_cast<const float4*>(Wv + qoff + kt + 32);
            po = *reinterpret_cast<const float4*>(Wo + ooff + (size_t)(kt + 32) * D_DIM);
        }

#pragma unroll
        for (int kk = 0; kk < 32; kk++) {
            const float a0 = Ms[ty][kk],      a1 = Ms[ty + 16][kk];
            const float b0 = Ws[kk][tx],      b1 = Ws[kk][tx + 16];
            acc[0][0] += a0 * b0; acc[0][1] += a0 * b1;
            acc[1][0] += a1 * b0; acc[1][1] += a1 * b1;
        }
        __syncthreads();
    }
#pragma unroll
    for (int i = 0; i < 2; i++) {
        const int k = k0 + ty + i * 16;
        const int j = k & 7;
        const int kp = (k & ~7) | (j < 4 ? 2 * j : 2 * (j - 4) + 1);
#pragma unroll
        for (int jj = 0; jj < 2; jj++) {
            const int n = n0 + tx + jj * 16;
            g_W[(size_t)n * D_DIM + kp] = __uint_as_float(f2tf32(acc[i][jj]));
        }
    }
}

// ---------------------------------------------------------------------------
// Main GEMM: out = x @ W_eff, tf32 mma.sync.
// BM=128, BN=112, BK=32, NSTG=3, **512 threads** (16 warps, 8m x 2n),
// warp tile 16x56, acc 28 regs -> <=63 regs -> 2 CTAs/SM = 32 warps (occ 50%).
// Single sync per mainloop iteration.
// ---------------------------------------------------------------------------
__global__ void __launch_bounds__(NTHR, 2) gemm_tf32_kernel(const float* __restrict__ x,
                                                            float* __restrict__ out) {
    extern __shared__ __align__(16) float smem[];

    const int tid   = threadIdx.x;
    const int wid   = tid >> 5;
    const int lane  = tid & 31;
    const int g     = lane >> 2;
    const int t     = lane & 3;
    const int warpM = wid & 7;     // 16 rows each
    const int warpN = wid >> 3;    // 56 cols each

    const int m0 = blockIdx.y * BM;
    const int n0 = blockIdx.x * BN;

    const uint32_t smem_base = smem_u32(smem);

    float acc[7][4];
#pragma unroll
    for (int j = 0; j < 7; j++)
#pragma unroll
        for (int q = 0; q < 4; q++) acc[j][q] = 0.f;

    auto load_stage = [&](int s, int kt) {
        const uint32_t aBase = smem_base + (uint32_t)(s * STG_F) * 4u;
        const uint32_t bBase = aBase + (uint32_t)AS_F * 4u;
        // A: 128x32 = 1024 16B chunks, 2 per thread
#pragma unroll
        for (int j = 0; j < 2; j++) {
            const int id  = tid + j * NTHR;
            const int row = id >> 3;
            const int c   = id & 7;
            CP16(aBase + (uint32_t)(row * A_STRIDE + c * 4) * 4u,
                 x + (size_t)(m0 + row) * D_DIM + kt + c * 4);
        }
        // B: 112x32 = 896 chunks, 1 per thread + 384 extra
        {
            const int row = tid >> 3;
            const int c   = tid & 7;
            CP16(bBase + (uint32_t)(row * B_STRIDE + c * 4) * 4u,
                 g_W + (size_t)(n0 + row) * D_DIM + kt + c * 4);
        }
        if (tid < 384) {
            const int id  = tid + NTHR;
            const int row = id >> 3;
            const int c   = id & 7;
            CP16(bBase + (uint32_t)(row * B_STRIDE + c * 4) * 4u,
                 g_W + (size_t)(n0 + row) * D_DIM + kt + c * 4);
        }
    };

    load_stage(0, 0);
    CP_COMMIT();
    load_stage(1, BK);
    CP_COMMIT();

    const int NIT = D_DIM / BK;   // 14
#pragma unroll 1
    for (int it = 0; it < NIT; it++) {
        CP_WAIT1();
        __syncthreads();

        if (it + 2 < NIT) load_stage((it + 2) % NSTG, (it + 2) * BK);
        CP_COMMIT();

        const float* As = smem + (it % NSTG) * STG_F;
        const float* Bs = As + AS_F;
        const float* Arow = As + (warpM * 16 + g) * A_STRIDE;
        const float* Brow = Bs + (warpN * 56 + g) * B_STRIDE;

#pragma unroll
        for (int kk = 0; kk < 4; kk++) {
            const int k0 = kk * 8;
            uint32_t af[4];
            af[0] = f2tf32(Arow[k0 + t]);
            af[1] = f2tf32(Arow[8 * A_STRIDE + k0 + t]);
            af[2] = f2tf32(Arow[k0 + t + 4]);
            af[3] = f2tf32(Arow[8 * A_STRIDE + k0 + t + 4]);
#pragma unroll
            for (int ni = 0; ni < 7; ni++) {
                // permuted layout: logical (k0+t, k0+t+4) at floats (k0+2t, k0+2t+1)
                const float2 bv = *reinterpret_cast<const float2*>(
                    Brow + ni * 8 * B_STRIDE + k0 + 2 * t);
                mma_tf32(acc[ni], af, __float_as_uint(bv.x), __float_as_uint(bv.y));
            }
        }
        // no trailing sync: next iteration's top sync provides the ordering
    }

    // ---- epilogue: rows (g, g+8), cols (2t, 2t+1) per ni
    const int r0 = m0 + warpM * 16 + g;
#pragma unroll
    for (int ni = 0; ni < 7; ni++) {
        const int c0 = n0 + warpN * 56 + ni * 8 + 2 * t;
        float2 v0, v1;
        v0.x = acc[ni][0]; v0.y = acc[ni][1];
        v1.x = acc[ni][2]; v1.y = acc[ni][3];
        *reinterpret_cast<float2*>(out + (size_t)r0 * D_DIM + c0)       = v0;
        *reinterpret_cast<float2*>(out + (size_t)(r0 + 8) * D_DIM + c0) = v1;
    }
}

// ---------------------------------------------------------------------------
extern "C" void kernel_launch(void* const* d_in, const int* in_sizes, int n_in,
                              void* d_out, int out_size) {
    const float* x  = (const float*)d_in[0];
    const float* Wq = (const float*)d_in[1];
    const float* Wk = (const float*)d_in[2];
    const float* Wv = (const float*)d_in[3];
    const float* Wo = (const float*)d_in[4];
    const float* A  = (const float*)d_in[5];
    const float* B  = (const float*)d_in[6];
    const float* C  = (const float*)d_in[7];

    cudaFuncSetAttribute(gemm_tf32_kernel, cudaFuncAttributeMaxDynamicSharedMemorySize,
                         SMEM_BYTES);

    weff_kernel<<<dim3(D_DIM / 32, D_DIM / 32), 256>>>(Wq, Wk, Wv, Wo, A, B, C);
    gemm_tf32_kernel<<<dim3(D_DIM / BN, MTOT / BM), NTHR, SMEM_BYTES>>>(x, (float*)d_out);
}